// round 1
// baseline (speedup 1.0000x reference)
#include <cuda_runtime.h>

// ---------------------------------------------------------------------------
// VectorQuantizerEMA on GB300
//   z:          (64, 64, 32, 32) f32   -> N = 65536 vectors of D = 64
//   embedding:  (1024, 64) f32
//   cluster_size (1024), ema_w (1024,64)
// Output (concatenated f32, tuple order):
//   z_q_st[4194304] | loss[1] | indices[65536] | new_cs[1024]
//   | new_ema_w[65536] | new_embedding[65536]
// ---------------------------------------------------------------------------

#define KCODES 1024
#define DDIM   64
#define NVEC   65536
#define TK     128

#define OFF_ZQ    0
#define OFF_LOSS  4194304
#define OFF_IDX   4194305
#define OFF_CS    4259841
#define OFF_EMAW  4260865
#define OFF_EMB   4326401

// Scratch (allocation-free: __device__ globals)
__device__ float g_counts[KCODES];
__device__ float g_dw[KCODES * DDIM];
__device__ float g_e2[KCODES];
__device__ float g_loss;
__device__ float g_nsum;

// ---------------------------------------------------------------------------
// Kernel 0: zero scratch + precompute |e_k|^2
// ---------------------------------------------------------------------------
__global__ void vq_init(const float* __restrict__ emb) {
    int i = blockIdx.x * blockDim.x + threadIdx.x;   // 0..65535
    if (i < KCODES * DDIM) g_dw[i] = 0.0f;
    if (i < KCODES) {
        g_counts[i] = 0.0f;
        const float* e = emb + i * DDIM;
        float s = 0.0f;
#pragma unroll
        for (int d = 0; d < DDIM; ++d) { float v = e[d]; s = fmaf(v, v, s); }
        g_e2[i] = s;
    }
    if (i == 0) { g_loss = 0.0f; g_nsum = 0.0f; }
}

// ---------------------------------------------------------------------------
// Kernel 1: distances + argmin + fused epilogue
//   score_k = |e_k|^2 + sum_d (-2 z_d) e_kd     (argmin == argmin of full d)
//   One thread per vector n; z held in registers pre-scaled by -2 so the
//   inner loop is pure FFMA chains fed by broadcast LDS.128 from the smem
//   code tile.
// ---------------------------------------------------------------------------
__global__ __launch_bounds__(256, 2)
void vq_main(const float* __restrict__ z, const float* __restrict__ emb,
             float* __restrict__ out) {
    __shared__ float4 sme[TK * (DDIM / 4)];  // 32 KB code tile
    __shared__ float  se2[TK];

    const int tid = threadIdx.x;
    const int n   = blockIdx.x * 256 + tid;        // vector id
    const int b   = n >> 10;                       // batch
    const int hw  = n & 1023;                      // h*32+w

    // Load z[n] (coalesced: per-d a warp reads 32 consecutive floats),
    // pre-multiplied by -2.
    const float* zb = z + (size_t)b * (DDIM * 1024) + hw;
    float4 zm[16];
#pragma unroll
    for (int q = 0; q < 16; ++q) {
        zm[q].x = -2.0f * zb[(q * 4 + 0) * 1024];
        zm[q].y = -2.0f * zb[(q * 4 + 1) * 1024];
        zm[q].z = -2.0f * zb[(q * 4 + 2) * 1024];
        zm[q].w = -2.0f * zb[(q * 4 + 3) * 1024];
    }

    float best = 3.4e38f;
    int   bidx = 0;

    for (int t = 0; t < KCODES / TK; ++t) {
        // cooperative tile load (contiguous 32 KB chunk)
        const float4* src = (const float4*)(emb + (size_t)t * TK * DDIM);
        for (int i = tid; i < TK * (DDIM / 4); i += 256) sme[i] = src[i];
        if (tid < TK) se2[tid] = g_e2[t * TK + tid];
        __syncthreads();

#pragma unroll 4
        for (int j = 0; j < TK; ++j) {
            float acc = se2[j];
            const float4* er = &sme[j * (DDIM / 4)];
#pragma unroll
            for (int q = 0; q < 16; ++q) {
                float4 e4 = er[q];          // broadcast LDS.128
                acc = fmaf(zm[q].x, e4.x, acc);
                acc = fmaf(zm[q].y, e4.y, acc);
                acc = fmaf(zm[q].z, e4.z, acc);
                acc = fmaf(zm[q].w, e4.w, acc);
            }
            if (acc < best) { best = acc; bidx = t * TK + j; }  // first-min, like argmin
        }
        __syncthreads();
    }

    // ---- epilogue ----
    out[OFF_IDX + n] = (float)bidx;
    atomicAdd(&g_counts[bidx], 1.0f);

    const float4* ev = (const float4*)(emb + (size_t)bidx * DDIM);  // L2-hot gather
    float* zq = out + OFF_ZQ + (size_t)b * (DDIM * 1024) + hw;
    float lsum = 0.0f;
#pragma unroll
    for (int q = 0; q < 16; ++q) {
        float4 e4 = ev[q];
        float zv[4] = { -0.5f * zm[q].x, -0.5f * zm[q].y,
                        -0.5f * zm[q].z, -0.5f * zm[q].w };
        float ee[4] = { e4.x, e4.y, e4.z, e4.w };
#pragma unroll
        for (int c = 0; c < 4; ++c) {
            int d = q * 4 + c;
            float diff = zv[c] - ee[c];
            lsum = fmaf(diff, diff, lsum);
            // straight-through value: z + (z_q - z)  (matches reference arithmetic)
            zq[d * 1024] = zv[c] + (ee[c] - zv[c]);
            atomicAdd(&g_dw[bidx * DDIM + d], zv[c]);
        }
    }
    // warp-reduce the loss partial, one atomic per warp
#pragma unroll
    for (int o = 16; o > 0; o >>= 1) lsum += __shfl_xor_sync(0xffffffffu, lsum, o);
    if ((tid & 31) == 0) atomicAdd(&g_loss, lsum);
}

// ---------------------------------------------------------------------------
// Kernel 2: new_cluster_size + n-sum + loss scalar (single block of 1024)
// ---------------------------------------------------------------------------
__global__ void vq_finalize1(const float* __restrict__ cs, float* __restrict__ out) {
    __shared__ float red[1024];
    int k = threadIdx.x;
    float ncs = fmaf(0.99f, cs[k], 0.01f * g_counts[k]);
    out[OFF_CS + k] = ncs;
    red[k] = ncs;
    __syncthreads();
#pragma unroll
    for (int s = 512; s > 0; s >>= 1) {
        if (k < s) red[k] += red[k + s];
        __syncthreads();
    }
    if (k == 0) {
        g_nsum = red[0];
        out[OFF_LOSS] = 0.25f * g_loss / 4194304.0f;
    }
}

// ---------------------------------------------------------------------------
// Kernel 3: new_ema_w and new_embedding (65536 elements, coalesced)
// ---------------------------------------------------------------------------
__global__ void vq_finalize2(const float* __restrict__ ema_w,
                             const float* __restrict__ out_cs_ro,  // = out (read back new_cs)
                             float* __restrict__ out) {
    int i = blockIdx.x * blockDim.x + threadIdx.x;  // 0..65535
    int k = i >> 6;
    float ne = fmaf(0.99f, ema_w[i], 0.01f * g_dw[i]);
    out[OFF_EMAW + i] = ne;
    float ncs = out_cs_ro[OFF_CS + k];
    float n = g_nsum;
    float csv = (ncs + 1e-5f) / (n + (float)KCODES * 1e-5f) * n;
    out[OFF_EMB + i] = ne / csv;
}

// ---------------------------------------------------------------------------
extern "C" void kernel_launch(void* const* d_in, const int* in_sizes, int n_in,
                              void* d_out, int out_size) {
    const float* z    = (const float*)d_in[0];
    const float* emb  = (const float*)d_in[1];
    const float* cs   = (const float*)d_in[2];
    const float* emaw = (const float*)d_in[3];
    float* out = (float*)d_out;

    vq_init<<<(KCODES * DDIM) / 256, 256>>>(emb);
    vq_main<<<NVEC / 256, 256>>>(z, emb, out);
    vq_finalize1<<<1, 1024>>>(cs, out);
    vq_finalize2<<<NVEC / 1024, 1024>>>(emaw, out, out);
}

// round 2
// speedup vs baseline: 1.0451x; 1.0451x over previous
#include <cuda_runtime.h>

// ---------------------------------------------------------------------------
// VectorQuantizerEMA on GB300 — Round 2: packed fp32 (fma.rn.f32x2) inner loop
//   z: (64, 64, 32, 32) f32 -> N = 65536 vectors of D = 64
//   embedding: (1024, 64) f32; cluster_size (1024); ema_w (1024,64)
// Output (concat f32): z_q_st[4194304] | loss[1] | indices[65536] |
//   new_cs[1024] | new_ema_w[65536] | new_embedding[65536]
// ---------------------------------------------------------------------------

#define KCODES 1024
#define DDIM   64
#define NVEC   65536
#define TK     128

#define OFF_ZQ    0
#define OFF_LOSS  4194304
#define OFF_IDX   4194305
#define OFF_CS    4259841
#define OFF_EMAW  4260865
#define OFF_EMB   4326401

__device__ float g_counts[KCODES];
__device__ float g_dw[KCODES * DDIM];
__device__ float g_e2[KCODES];
__device__ float g_loss;
__device__ float g_nsum;

// ---------------------------------------------------------------------------
// Kernel 0: zero scratch + precompute |e_k|^2
// ---------------------------------------------------------------------------
__global__ void vq_init(const float* __restrict__ emb) {
    int i = blockIdx.x * blockDim.x + threadIdx.x;   // 0..65535
    if (i < KCODES * DDIM) g_dw[i] = 0.0f;
    if (i < KCODES) {
        g_counts[i] = 0.0f;
        const float* e = emb + i * DDIM;
        float s = 0.0f;
#pragma unroll
        for (int d = 0; d < DDIM; ++d) { float v = e[d]; s = fmaf(v, v, s); }
        g_e2[i] = s;
    }
    if (i == 0) { g_loss = 0.0f; g_nsum = 0.0f; }
}

// ---------------------------------------------------------------------------
// Kernel 1: distances + argmin + fused epilogue, f32x2 packed FMA.
//   score_k = |e_k|^2 + sum_d (-2 z_d) e_kd
//   z pre-scaled by -2, packed into 32 f32x2 registers. Code rows stream
//   from smem via ld.shared.v2.b64 (pairs land directly in 64-bit regs,
//   no packing instructions), feeding fma.rn.f32x2 (FFMA2: 2 fp32 MAC/lane).
// ---------------------------------------------------------------------------
__global__ __launch_bounds__(256, 2)
void vq_main(const float* __restrict__ z, const float* __restrict__ emb,
             float* __restrict__ out) {
    __shared__ float4 sme[TK * (DDIM / 4)];  // 32 KB code tile
    __shared__ float  se2[TK];

    const int tid = threadIdx.x;
    const int n   = blockIdx.x * 256 + tid;
    const int b   = n >> 10;
    const int hw  = n & 1023;

    // z[n] pre-scaled by -2, packed as (d, d+1) f32x2 pairs.
    const float* zb = z + (size_t)b * (DDIM * 1024) + hw;
    unsigned long long zp[32];
#pragma unroll
    for (int q = 0; q < 32; ++q) {
        float a = -2.0f * zb[(2 * q + 0) * 1024];
        float c = -2.0f * zb[(2 * q + 1) * 1024];
        asm("mov.b64 %0, {%1, %2};" : "=l"(zp[q]) : "f"(a), "f"(c));
    }

    float best = 3.4e38f;
    int   bidx = 0;

    const unsigned int smem_base =
        (unsigned int)__cvta_generic_to_shared(&sme[0]);

    for (int t = 0; t < KCODES / TK; ++t) {
        const float4* src = (const float4*)(emb + (size_t)t * TK * DDIM);
        for (int i = tid; i < TK * (DDIM / 4); i += 256) sme[i] = src[i];
        if (tid < TK) se2[tid] = g_e2[t * TK + tid];
        __syncthreads();

#pragma unroll 2
        for (int j = 0; j < TK; ++j) {
            const unsigned int row = smem_base + (unsigned int)j * (DDIM * 4);
            unsigned long long acc0 = 0ULL, acc1 = 0ULL;
#pragma unroll
            for (int q = 0; q < 16; ++q) {
                unsigned long long p0, p1;
                asm("ld.shared.v2.b64 {%0, %1}, [%2];"
                    : "=l"(p0), "=l"(p1) : "r"(row + q * 16));
                asm("fma.rn.f32x2 %0, %1, %2, %0;"
                    : "+l"(acc0) : "l"(zp[2 * q + 0]), "l"(p0));
                asm("fma.rn.f32x2 %0, %1, %2, %0;"
                    : "+l"(acc1) : "l"(zp[2 * q + 1]), "l"(p1));
            }
            float lo0, hi0, lo1, hi1;
            asm("mov.b64 {%0, %1}, %2;" : "=f"(lo0), "=f"(hi0) : "l"(acc0));
            asm("mov.b64 {%0, %1}, %2;" : "=f"(lo1), "=f"(hi1) : "l"(acc1));
            float score = se2[j] + ((lo0 + hi0) + (lo1 + hi1));
            if (score < best) { best = score; bidx = t * TK + j; }
        }
        __syncthreads();
    }

    // ---- epilogue ----
    out[OFF_IDX + n] = (float)bidx;
    atomicAdd(&g_counts[bidx], 1.0f);

    const float4* ev = (const float4*)(emb + (size_t)bidx * DDIM);
    float* zq = out + OFF_ZQ + (size_t)b * (DDIM * 1024) + hw;
    float lsum = 0.0f;
#pragma unroll
    for (int q = 0; q < 16; ++q) {
        float4 e4 = ev[q];
        float ee[4] = { e4.x, e4.y, e4.z, e4.w };
#pragma unroll
        for (int c = 0; c < 4; ++c) {
            int d = q * 4 + c;
            // recover z_d from packed (-2 z) pairs
            float lo, hi;
            asm("mov.b64 {%0, %1}, %2;" : "=f"(lo), "=f"(hi) : "l"(zp[d >> 1]));
            float zv = -0.5f * ((d & 1) ? hi : lo);
            float diff = zv - ee[c];
            lsum = fmaf(diff, diff, lsum);
            zq[d * 1024] = zv + (ee[c] - zv);   // straight-through value
            atomicAdd(&g_dw[bidx * DDIM + d], zv);
        }
    }
#pragma unroll
    for (int o = 16; o > 0; o >>= 1) lsum += __shfl_xor_sync(0xffffffffu, lsum, o);
    if ((tid & 31) == 0) atomicAdd(&g_loss, lsum);
}

// ---------------------------------------------------------------------------
// Kernel 2: new_cluster_size + n-sum + loss scalar
// ---------------------------------------------------------------------------
__global__ void vq_finalize1(const float* __restrict__ cs, float* __restrict__ out) {
    __shared__ float red[1024];
    int k = threadIdx.x;
    float ncs = fmaf(0.99f, cs[k], 0.01f * g_counts[k]);
    out[OFF_CS + k] = ncs;
    red[k] = ncs;
    __syncthreads();
#pragma unroll
    for (int s = 512; s > 0; s >>= 1) {
        if (k < s) red[k] += red[k + s];
        __syncthreads();
    }
    if (k == 0) {
        g_nsum = red[0];
        out[OFF_LOSS] = 0.25f * g_loss / 4194304.0f;
    }
}

// ---------------------------------------------------------------------------
// Kernel 3: new_ema_w and new_embedding
// ---------------------------------------------------------------------------
__global__ void vq_finalize2(const float* __restrict__ ema_w,
                             const float* __restrict__ out_cs_ro,
                             float* __restrict__ out) {
    int i = blockIdx.x * blockDim.x + threadIdx.x;  // 0..65535
    int k = i >> 6;
    float ne = fmaf(0.99f, ema_w[i], 0.01f * g_dw[i]);
    out[OFF_EMAW + i] = ne;
    float ncs = out_cs_ro[OFF_CS + k];
    float n = g_nsum;
    float csv = (ncs + 1e-5f) / (n + (float)KCODES * 1e-5f) * n;
    out[OFF_EMB + i] = ne / csv;
}

// ---------------------------------------------------------------------------
extern "C" void kernel_launch(void* const* d_in, const int* in_sizes, int n_in,
                              void* d_out, int out_size) {
    const float* z    = (const float*)d_in[0];
    const float* emb  = (const float*)d_in[1];
    const float* cs   = (const float*)d_in[2];
    const float* emaw = (const float*)d_in[3];
    float* out = (float*)d_out;

    vq_init<<<(KCODES * DDIM) / 256, 256>>>(emb);
    vq_main<<<NVEC / 256, 256>>>(z, emb, out);
    vq_finalize1<<<1, 1024>>>(cs, out);
    vq_finalize2<<<NVEC / 1024, 1024>>>(emaw, out, out);
}

// round 3
// speedup vs baseline: 1.3774x; 1.3179x over previous
#include <cuda_runtime.h>

// ---------------------------------------------------------------------------
// VectorQuantizerEMA on GB300 — Round 3: 3xTF32 mma.sync distance GEMM
//   argmin_k |z-e_k|^2  ==  argmax_k ( z.e_k - |e_k|^2/2 )
//   GEMM M=65536 (vectors) x N=1024 (codes) x K=64, tf32 3-way split:
//     dot ~= z_hi.e_hi + z_lo.e_hi + z_hi.e_lo   (K_eff = 192 = 24 k8-tiles)
// ---------------------------------------------------------------------------

#define KCODES 1024
#define DDIM   64
#define NVEC   65536

#define OFF_ZQ    0
#define OFF_LOSS  4194304
#define OFF_IDX   4194305
#define OFF_CS    4259841
#define OFF_EMAW  4260865
#define OFF_EMB   4326401

#define MTILE   256          // rows per CTA
#define CHUNK   64           // codes per smem chunk
#define NCHUNK  (KCODES / CHUNK)
#define KT      24           // k8-tiles (3 x 8)
#define STRIP   52           // floats per (code,tig) strip (48 data + 4 pad)

#define CHUNK_FLOATS (CHUNK * 4 * STRIP)          // 13312 floats = 53248 B
#define SMEM_E2_OFF  (2 * CHUNK_FLOATS)           // after the two B buffers
#define SMEM_FLOATS  (2 * CHUNK_FLOATS + KCODES)  // 110592 B total
#define ZSTRIDE 68                                 // zstage row stride (floats)

// Scratch (__device__ globals; zero-initialized at load, re-zeroed per call)
__device__ float g_counts[KCODES];
__device__ float g_dw[KCODES * DDIM];
__device__ float g_e2[KCODES];
__device__ float g_B[KCODES * 4 * STRIP];   // permuted tf32 code strips
__device__ float g_loss;
__device__ float g_nsum;

// ---------------------------------------------------------------------------
__device__ __forceinline__ unsigned f2tf32(float f) {
    unsigned u;
    asm("cvt.rna.tf32.f32 %0, %1;" : "=r"(u) : "f"(f));
    return u;
}

// ---------------------------------------------------------------------------
// Kernel 0: zero scratch, |e|^2, and build permuted tf32 strips for B.
// Strip layout: g_B[((code*4 + tig)*STRIP) + kt*2 + {0,1}]
//   kt 0..7  : e_hi at d = (kt%8)*8 + tig / +4   (pairs with z_hi)
//   kt 8..15 : e_hi                              (pairs with z_lo)
//   kt 16..23: e_lo                              (pairs with z_hi)
// ---------------------------------------------------------------------------
__global__ void vq_prep(const float* __restrict__ emb) {
    int i = blockIdx.x * blockDim.x + threadIdx.x;   // 0..65535
    if (i < KCODES * DDIM) g_dw[i] = 0.0f;
    if (i == 0) { g_loss = 0.0f; g_nsum = 0.0f; }
    if (i < KCODES) {
        g_counts[i] = 0.0f;
        const float* e = emb + i * DDIM;
        float s = 0.0f;
#pragma unroll
        for (int d = 0; d < DDIM; ++d) { float v = e[d]; s = fmaf(v, v, s); }
        g_e2[i] = s;
    }
    if (i < KCODES * 4) {
        int code = i >> 2, tig = i & 3;
        const float* e = emb + code * DDIM;
        float* strip = g_B + (size_t)i * STRIP;
#pragma unroll
        for (int kt = 0; kt < KT; ++kt) {
            int d0 = (kt & 7) * 8 + tig;
            float v0 = e[d0], v1 = e[d0 + 4];
            unsigned h0 = f2tf32(v0), h1 = f2tf32(v1);
            unsigned o0, o1;
            if (kt < 16) { o0 = h0; o1 = h1; }
            else {
                o0 = f2tf32(v0 - __uint_as_float(h0));
                o1 = f2tf32(v1 - __uint_as_float(h1));
            }
            strip[kt * 2 + 0] = __uint_as_float(o0);
            strip[kt * 2 + 1] = __uint_as_float(o1);
        }
    }
}

// ---------------------------------------------------------------------------
#define MMA(C, A, b0, b1)                                                   \
    asm volatile("mma.sync.aligned.m16n8k8.row.col.f32.tf32.tf32.f32 "      \
                 "{%0,%1,%2,%3}, {%4,%5,%6,%7}, {%8,%9}, {%0,%1,%2,%3};"    \
                 : "+f"(C[0]), "+f"(C[1]), "+f"(C[2]), "+f"(C[3])           \
                 : "r"(A[0]), "r"(A[1]), "r"(A[2]), "r"(A[3]),              \
                   "r"(b0), "r"(b1))

#define ASEL(kt) ((kt) < 8 ? ah[(kt)] : (kt) < 16 ? al[(kt) - 8] : ah[(kt) - 16])

__device__ __forceinline__ void upd(float v, int i, float& b, int& bi) {
    if (v > b) { b = v; bi = i; }   // strict >  => first index wins ties
}

// ---------------------------------------------------------------------------
// Kernel 1: GEMM + argmax.  512 threads (16 warps), warp owns 16 rows.
// ---------------------------------------------------------------------------
__global__ __launch_bounds__(512, 1)
void vq_mma(const float* __restrict__ z, float* __restrict__ out) {
    extern __shared__ float smem[];
    float* se2 = smem + SMEM_E2_OFF;

    const int tid  = threadIdx.x;
    const int wid  = tid >> 5;
    const int lane = tid & 31;
    const int grp  = lane >> 2;
    const int tig  = lane & 3;
    const int m0   = blockIdx.x * MTILE;

    // ---- stage z tile (coalesced: n fastest) into smem[r*68 + d] ----
    const int   zb  = m0 >> 10;            // batch (MTILE=256 divides 1024)
    const int   hw0 = m0 & 1023;
    const float* zsrc = z + (size_t)zb * (DDIM * 1024) + hw0;
    for (int i = tid; i < MTILE * DDIM; i += 512) {
        int d = i >> 8, r = i & 255;
        smem[r * ZSTRIDE + d] = zsrc[d * 1024 + r];
    }
    for (int i = tid; i < KCODES; i += 512) se2[i] = g_e2[i];
    __syncthreads();

    // ---- A fragments (z_hi / z_lo), 16x8 per k-tile ----
    unsigned ah[8][4], al[8][4];
    const int row0 = (wid << 4) + grp;     // local row (0..255)
#pragma unroll
    for (int kt = 0; kt < 8; ++kt) {
#pragma unroll
        for (int p = 0; p < 4; ++p) {
            int r = row0 + ((p & 1) << 3);
            int c = kt * 8 + tig + ((p >> 1) << 2);
            float v = smem[r * ZSTRIDE + c];
            unsigned hi = f2tf32(v);
            ah[kt][p] = hi;
            al[kt][p] = f2tf32(v - __uint_as_float(hi));
        }
    }
    __syncthreads();   // zstage dead; region reused as B buffer 0

    // ---- B chunk pipeline (cp.async, double-buffered) ----
    const unsigned sb = (unsigned)__cvta_generic_to_shared(smem);
    {   // chunk 0
        size_t src = __cvta_generic_to_global(g_B);
        for (int i = tid; i < CHUNK_FLOATS / 4; i += 512)
            asm volatile("cp.async.ca.shared.global [%0], [%1], 16;"
                         :: "r"(sb + i * 16), "l"(src + (size_t)i * 16));
        asm volatile("cp.async.commit_group;");
    }

    float best0 = -3.4e38f, best8 = -3.4e38f;
    int   idx0 = 0, idx8 = 0;

    for (int ch = 0; ch < NCHUNK; ++ch) {
        if (ch + 1 < NCHUNK) {
            unsigned dst = sb + ((ch + 1) & 1) * (CHUNK_FLOATS * 4);
            size_t   src = __cvta_generic_to_global(g_B) +
                           (size_t)(ch + 1) * CHUNK_FLOATS * 4;
            for (int i = tid; i < CHUNK_FLOATS / 4; i += 512)
                asm volatile("cp.async.ca.shared.global [%0], [%1], 16;"
                             :: "r"(dst + i * 16), "l"(src + (size_t)i * 16));
            asm volatile("cp.async.commit_group;");
            asm volatile("cp.async.wait_group 1;");
        } else {
            asm volatile("cp.async.wait_group 0;");
        }
        __syncthreads();

        const unsigned bufb = sb + (ch & 1) * (CHUNK_FLOATS * 4);
#pragma unroll 1
        for (int s = 0; s < 8; s += 2) {   // two n8 tiles in flight
            const int nb0 = ch * CHUNK + s * 8;
            const int nb1 = nb0 + 8;
            float c0[4], c1[4];
            c0[0] = c0[2] = -0.5f * se2[nb0 + 2 * tig];
            c0[1] = c0[3] = -0.5f * se2[nb0 + 2 * tig + 1];
            c1[0] = c1[2] = -0.5f * se2[nb1 + 2 * tig];
            c1[1] = c1[3] = -0.5f * se2[nb1 + 2 * tig + 1];

            const unsigned a0 = bufb + (((s * 8 + grp) * 4 + tig) * STRIP) * 4;
            const unsigned a1 = a0 + (8 * 4 * STRIP) * 4;
#pragma unroll
            for (int kk = 0; kk < KT; kk += 2) {
                unsigned p0, p1, p2, p3, q0, q1, q2, q3;
                asm volatile("ld.shared.v4.b32 {%0,%1,%2,%3}, [%4];"
                             : "=r"(p0), "=r"(p1), "=r"(p2), "=r"(p3)
                             : "r"(a0 + kk * 8));
                asm volatile("ld.shared.v4.b32 {%0,%1,%2,%3}, [%4];"
                             : "=r"(q0), "=r"(q1), "=r"(q2), "=r"(q3)
                             : "r"(a1 + kk * 8));
                MMA(c0, ASEL(kk),     p0, p1);
                MMA(c1, ASEL(kk),     q0, q1);
                MMA(c0, ASEL(kk + 1), p2, p3);
                MMA(c1, ASEL(kk + 1), q2, q3);
            }
            upd(c0[0], nb0 + 2 * tig,     best0, idx0);
            upd(c0[1], nb0 + 2 * tig + 1, best0, idx0);
            upd(c0[2], nb0 + 2 * tig,     best8, idx8);
            upd(c0[3], nb0 + 2 * tig + 1, best8, idx8);
            upd(c1[0], nb1 + 2 * tig,     best0, idx0);
            upd(c1[1], nb1 + 2 * tig + 1, best0, idx0);
            upd(c1[2], nb1 + 2 * tig,     best8, idx8);
            upd(c1[3], nb1 + 2 * tig + 1, best8, idx8);
        }
        __syncthreads();
    }

    // ---- reduce argmax over the 4 lanes of each row group ----
#pragma unroll
    for (int m = 1; m <= 2; m <<= 1) {
        float ob = __shfl_xor_sync(0xffffffffu, best0, m);
        int   oi = __shfl_xor_sync(0xffffffffu, idx0,  m);
        if (ob > best0 || (ob == best0 && oi < idx0)) { best0 = ob; idx0 = oi; }
        ob = __shfl_xor_sync(0xffffffffu, best8, m);
        oi = __shfl_xor_sync(0xffffffffu, idx8,  m);
        if (ob > best8 || (ob == best8 && oi < idx8)) { best8 = ob; idx8 = oi; }
    }
    if (tig == 0) {
        int n = m0 + row0;
        out[OFF_IDX + n]     = (float)idx0;
        out[OFF_IDX + n + 8] = (float)idx8;
    }
}

// ---------------------------------------------------------------------------
// Kernel 2: epilogue — z_q, loss partials, counts, dw (one thread per vector)
// ---------------------------------------------------------------------------
__global__ __launch_bounds__(256)
void vq_epi(const float* __restrict__ z, const float* __restrict__ emb,
            float* __restrict__ out) {
    const int n  = blockIdx.x * 256 + threadIdx.x;
    const int b  = n >> 10;
    const int hw = n & 1023;

    const int idx = (int)out[OFF_IDX + n];
    atomicAdd(&g_counts[idx], 1.0f);

    const float*  zbp = z   + (size_t)b * (DDIM * 1024) + hw;
    float*        zq  = out + OFF_ZQ + (size_t)b * (DDIM * 1024) + hw;
    const float4* ev  = (const float4*)(emb + (size_t)idx * DDIM);
    float lsum = 0.0f;
#pragma unroll
    for (int q = 0; q < 16; ++q) {
        float4 e4 = ev[q];
        float ee[4] = { e4.x, e4.y, e4.z, e4.w };
#pragma unroll
        for (int c = 0; c < 4; ++c) {
            int d = q * 4 + c;
            float zv = zbp[d * 1024];
            float diff = zv - ee[c];
            lsum = fmaf(diff, diff, lsum);
            zq[d * 1024] = zv + (ee[c] - zv);   // straight-through, ref arithmetic
            atomicAdd(&g_dw[idx * DDIM + d], zv);
        }
    }
#pragma unroll
    for (int o = 16; o > 0; o >>= 1) lsum += __shfl_xor_sync(0xffffffffu, lsum, o);
    if ((threadIdx.x & 31) == 0) atomicAdd(&g_loss, lsum);
}

// ---------------------------------------------------------------------------
// Kernel 3: new_cluster_size + n-sum + loss scalar
// ---------------------------------------------------------------------------
__global__ void vq_finalize1(const float* __restrict__ cs, float* __restrict__ out) {
    __shared__ float red[1024];
    int k = threadIdx.x;
    float ncs = fmaf(0.99f, cs[k], 0.01f * g_counts[k]);
    out[OFF_CS + k] = ncs;
    red[k] = ncs;
    __syncthreads();
#pragma unroll
    for (int s = 512; s > 0; s >>= 1) {
        if (k < s) red[k] += red[k + s];
        __syncthreads();
    }
    if (k == 0) {
        g_nsum = red[0];
        out[OFF_LOSS] = 0.25f * g_loss / 4194304.0f;
    }
}

// ---------------------------------------------------------------------------
// Kernel 4: new_ema_w and new_embedding
// ---------------------------------------------------------------------------
__global__ void vq_finalize2(const float* __restrict__ ema_w,
                             const float* __restrict__ out_cs_ro,
                             float* __restrict__ out) {
    int i = blockIdx.x * blockDim.x + threadIdx.x;  // 0..65535
    int k = i >> 6;
    float ne = fmaf(0.99f, ema_w[i], 0.01f * g_dw[i]);
    out[OFF_EMAW + i] = ne;
    float ncs = out_cs_ro[OFF_CS + k];
    float nn = g_nsum;
    float csv = (ncs + 1e-5f) / (nn + (float)KCODES * 1e-5f) * nn;
    out[OFF_EMB + i] = ne / csv;
}

// ---------------------------------------------------------------------------
extern "C" void kernel_launch(void* const* d_in, const int* in_sizes, int n_in,
                              void* d_out, int out_size) {
    const float* z    = (const float*)d_in[0];
    const float* emb  = (const float*)d_in[1];
    const float* cs   = (const float*)d_in[2];
    const float* emaw = (const float*)d_in[3];
    float* out = (float*)d_out;

    cudaFuncSetAttribute(vq_mma, cudaFuncAttributeMaxDynamicSharedMemorySize,
                         SMEM_FLOATS * 4);

    vq_prep<<<256, 256>>>(emb);
    vq_mma<<<NVEC / MTILE, 512, SMEM_FLOATS * 4>>>(z, out);
    vq_epi<<<NVEC / 256, 256>>>(z, emb, out);
    vq_finalize1<<<1, 1024>>>(cs, out);
    vq_finalize2<<<NVEC / 1024, 1024>>>(emaw, out, out);
}

// round 5
// speedup vs baseline: 1.8637x; 1.3531x over previous
#include <cuda_runtime.h>
#include <cuda_fp16.h>
#include <cstdint>

// ---------------------------------------------------------------------------
// VectorQuantizerEMA on GB300 — Round 5: fp16 m16n8k16 mma.sync, 3-way split
//   argmin_k |z-e_k|^2  ==  argmax_k ( z.e_k - |e_k|^2/2 )
//   dot ~= zh.eh + zl.eh + zh.el   (fp16 mantissa == tf32 mantissa)
//   12 k16-mmas per 16x8 tile (vs 24 k8 tf32 in R3), dedup'd B (8 k-blocks).
// NOTE: tcgen05 is toolchain-blocked (harness PTX targets sm_103, no 'a').
// ---------------------------------------------------------------------------

#define KCODES 1024
#define DDIM   64
#define NVEC   65536

#define OFF_ZQ    0
#define OFF_LOSS  4194304
#define OFF_IDX   4194305
#define OFF_CS    4259841
#define OFF_EMAW  4260865
#define OFF_EMB   4326401

#define MTILE   256          // rows per CTA
#define CHUNK   64           // codes per smem chunk (8 n8-tiles)
#define NCHUNK  (KCODES / CHUNK)

// B chunk: 8 tiles x 4 slots x 32 lanes x 4 words(half2) = 4096 words = 16 KB
#define CHUNK_WORDS  4096
#define SMEM_E2_OFF  17408                 // floats (after zstage/B region)
#define SMEM_FLOATS  (17408 + 1024)        // 73728 bytes
#define ZSTRIDE 68

// Scratch
__device__ float    g_counts[KCODES];
__device__ float    g_dw[KCODES * DDIM];
__device__ float    g_e2[KCODES];
__device__ unsigned g_B[NCHUNK * CHUNK_WORDS];   // 256 KB packed half2
__device__ float    g_loss;
__device__ float    g_nsum;

// ---------------------------------------------------------------------------
__device__ __forceinline__ unsigned pack_h2(float a, float b) {
    __half ha = __float2half_rn(a), hb = __float2half_rn(b);
    return (unsigned)__half_as_ushort(ha) |
           ((unsigned)__half_as_ushort(hb) << 16);
}

// ---------------------------------------------------------------------------
// Kernel 0: zero scratch, |e|^2, build packed fp16 B fragments.
// Word i of g_B: chunk=i>>12, rem=i&4095: s=rem>>9, q=(rem>>7)&3,
//   lane=(rem>>2)&31 (grp=lane>>2, tig=lane&3), j=rem&3; strip word w=q*4+j:
//   bk=w>>1 (0-3: e_hi d-block bk, 4-7: e_lo d-block bk-4), h=w&1;
//   halves at d = (bk&3)*16 + tig*2 + h*8 + {0,1}; code = chunk*64+s*8+grp.
// ---------------------------------------------------------------------------
__global__ __launch_bounds__(256)
void vq_prep(const float* __restrict__ emb) {
    int i = blockIdx.x * 256 + threadIdx.x;         // 0..65535
    if (i < KCODES * DDIM) g_dw[i] = 0.0f;
    if (i == 0) { g_loss = 0.0f; g_nsum = 0.0f; }
    if (i < KCODES) {
        g_counts[i] = 0.0f;
        const float* e = emb + i * DDIM;
        float s = 0.0f;
#pragma unroll
        for (int d = 0; d < DDIM; ++d) { float v = e[d]; s = fmaf(v, v, s); }
        g_e2[i] = s;
    }
    {
        int chunk = i >> 12;
        int rem   = i & 4095;
        int s    = rem >> 9;
        int q    = (rem >> 7) & 3;
        int lane = (rem >> 2) & 31;
        int j    = rem & 3;
        int grp = lane >> 2, tig = lane & 3;
        int w = q * 4 + j;
        int bk = w >> 1, h = w & 1;
        int code = chunk * 64 + s * 8 + grp;
        int d = (bk & 3) * 16 + tig * 2 + h * 8;
        float v0 = emb[code * DDIM + d];
        float v1 = emb[code * DDIM + d + 1];
        unsigned o;
        if (bk < 4) {
            o = pack_h2(v0, v1);
        } else {
            float h0 = __half2float(__float2half_rn(v0));
            float h1 = __half2float(__float2half_rn(v1));
            o = pack_h2(v0 - h0, v1 - h1);
        }
        g_B[i] = o;
    }
}

// ---------------------------------------------------------------------------
#define MMAF16(C, A, b0, b1)                                                \
    asm volatile("mma.sync.aligned.m16n8k16.row.col.f32.f16.f16.f32 "       \
                 "{%0,%1,%2,%3}, {%4,%5,%6,%7}, {%8,%9}, {%0,%1,%2,%3};"    \
                 : "+f"(C[0]), "+f"(C[1]), "+f"(C[2]), "+f"(C[3])           \
                 : "r"(A[0]), "r"(A[1]), "r"(A[2]), "r"(A[3]),              \
                   "r"(b0), "r"(b1))

#define ASEL(kt) ((kt) < 4 ? ah[(kt)] : (kt) < 8 ? al[(kt) - 4] : ah[(kt) - 8])

__device__ __forceinline__ void upd(float v, int i, float& b, int& bi) {
    if (v > b) { b = v; bi = i; }   // strict > => first index wins ties
}

// ---------------------------------------------------------------------------
// Kernel 1: GEMM + argmax.  512 threads (16 warps), warp owns 16 rows.
// ---------------------------------------------------------------------------
__global__ __launch_bounds__(512, 1)
void vq_mma(const float* __restrict__ z, float* __restrict__ out) {
    extern __shared__ float smem[];
    float* se2 = smem + SMEM_E2_OFF;

    const int tid  = threadIdx.x;
    const int wid  = tid >> 5;
    const int lane = tid & 31;
    const int grp  = lane >> 2;
    const int tig  = lane & 3;
    const int m0   = blockIdx.x * MTILE;

    // ---- stage z tile (coalesced over rows) into smem[r*68 + d] ----
    const int   zb  = m0 >> 10;
    const int   hw0 = m0 & 1023;
    const float* zsrc = z + (size_t)zb * (DDIM * 1024) + hw0;
    for (int i = tid; i < MTILE * DDIM; i += 512) {
        int d = i >> 8, r = i & 255;
        smem[r * ZSTRIDE + d] = zsrc[d * 1024 + r];
    }
    for (int i = tid; i < KCODES; i += 512) se2[i] = g_e2[i];
    __syncthreads();

    // ---- A fragments (z_hi / z_lo), 4 k16-tiles each ----
    unsigned ah[4][4], al[4][4];
    const int row0 = (wid << 4) + grp;     // local row (0..255)
#pragma unroll
    for (int kt = 0; kt < 4; ++kt) {
#pragma unroll
        for (int p = 0; p < 4; ++p) {
            int r = row0 + ((p & 1) << 3);
            int c = kt * 16 + tig * 2 + ((p >> 1) << 3);
            float v0 = smem[r * ZSTRIDE + c];
            float v1 = smem[r * ZSTRIDE + c + 1];
            float h0 = __half2float(__float2half_rn(v0));
            float h1 = __half2float(__float2half_rn(v1));
            ah[kt][p] = pack_h2(v0, v1);
            al[kt][p] = pack_h2(v0 - h0, v1 - h1);
        }
    }
    __syncthreads();   // zstage dead; region reused as B double buffer

    // ---- B chunk pipeline (cp.async, double-buffered) ----
    const unsigned sb = (unsigned)__cvta_generic_to_shared(smem);
    {   // chunk 0
        size_t src = __cvta_generic_to_global(g_B);
        for (int i = tid; i < CHUNK_WORDS / 4; i += 512)
            asm volatile("cp.async.ca.shared.global [%0], [%1], 16;"
                         :: "r"(sb + i * 16), "l"(src + (size_t)i * 16));
        asm volatile("cp.async.commit_group;");
    }

    float best0 = -3.4e38f, best8 = -3.4e38f;
    int   idx0 = 0, idx8 = 0;

    for (int ch = 0; ch < NCHUNK; ++ch) {
        if (ch + 1 < NCHUNK) {
            unsigned dst = sb + ((ch + 1) & 1) * (CHUNK_WORDS * 4);
            size_t   src = __cvta_generic_to_global(g_B) +
                           (size_t)(ch + 1) * CHUNK_WORDS * 4;
            for (int i = tid; i < CHUNK_WORDS / 4; i += 512)
                asm volatile("cp.async.ca.shared.global [%0], [%1], 16;"
                             :: "r"(dst + i * 16), "l"(src + (size_t)i * 16));
            asm volatile("cp.async.commit_group;");
            asm volatile("cp.async.wait_group 1;");
        } else {
            asm volatile("cp.async.wait_group 0;");
        }
        __syncthreads();

        const unsigned bufb = sb + (ch & 1) * (CHUNK_WORDS * 4) + lane * 16;
#pragma unroll 1
        for (int s = 0; s < 8; s += 2) {   // two n8 tiles in flight
            const int nb0 = ch * CHUNK + s * 8;
            const int nb1 = nb0 + 8;
            float c0[4], c1[4];
            c0[0] = c0[2] = -0.5f * se2[nb0 + 2 * tig];
            c0[1] = c0[3] = -0.5f * se2[nb0 + 2 * tig + 1];
            c1[0] = c1[2] = -0.5f * se2[nb1 + 2 * tig];
            c1[1] = c1[3] = -0.5f * se2[nb1 + 2 * tig + 1];

            // conflict-free fragment loads: lane-linear 16B slots
            unsigned bw0[16], bw1[16];
#pragma unroll
            for (int q = 0; q < 4; ++q) {
                asm volatile("ld.shared.v4.b32 {%0,%1,%2,%3}, [%4];"
                             : "=r"(bw0[q * 4]), "=r"(bw0[q * 4 + 1]),
                               "=r"(bw0[q * 4 + 2]), "=r"(bw0[q * 4 + 3])
                             : "r"(bufb + (s * 4 + q) * 512));
                asm volatile("ld.shared.v4.b32 {%0,%1,%2,%3}, [%4];"
                             : "=r"(bw1[q * 4]), "=r"(bw1[q * 4 + 1]),
                               "=r"(bw1[q * 4 + 2]), "=r"(bw1[q * 4 + 3])
                             : "r"(bufb + ((s + 1) * 4 + q) * 512));
            }
#pragma unroll
            for (int kt = 0; kt < 12; ++kt) {
                const int bi = (kt < 4) ? kt : kt - 4;   // dedup'd e_hi reuse
                MMAF16(c0, ASEL(kt), bw0[bi * 2], bw0[bi * 2 + 1]);
                MMAF16(c1, ASEL(kt), bw1[bi * 2], bw1[bi * 2 + 1]);
            }
            upd(c0[0], nb0 + 2 * tig,     best0, idx0);
            upd(c0[1], nb0 + 2 * tig + 1, best0, idx0);
            upd(c0[2], nb0 + 2 * tig,     best8, idx8);
            upd(c0[3], nb0 + 2 * tig + 1, best8, idx8);
            upd(c1[0], nb1 + 2 * tig,     best0, idx0);
            upd(c1[1], nb1 + 2 * tig + 1, best0, idx0);
            upd(c1[2], nb1 + 2 * tig,     best8, idx8);
            upd(c1[3], nb1 + 2 * tig + 1, best8, idx8);
        }
        __syncthreads();
    }

    // ---- reduce argmax over the 4 lanes of each row group ----
#pragma unroll
    for (int m = 1; m <= 2; m <<= 1) {
        float ob = __shfl_xor_sync(0xffffffffu, best0, m);
        int   oi = __shfl_xor_sync(0xffffffffu, idx0,  m);
        if (ob > best0 || (ob == best0 && oi < idx0)) { best0 = ob; idx0 = oi; }
        ob = __shfl_xor_sync(0xffffffffu, best8, m);
        oi = __shfl_xor_sync(0xffffffffu, idx8,  m);
        if (ob > best8 || (ob == best8 && oi < idx8)) { best8 = ob; idx8 = oi; }
    }
    if (tig == 0) {
        int n = m0 + row0;
        out[OFF_IDX + n]     = (float)idx0;
        out[OFF_IDX + n + 8] = (float)idx8;
    }
}

// ---------------------------------------------------------------------------
// Kernel 2: epilogue — z_q, loss partials, counts, dw
// ---------------------------------------------------------------------------
__global__ __launch_bounds__(256)
void vq_epi(const float* __restrict__ z, const float* __restrict__ emb,
            float* __restrict__ out) {
    const int n  = blockIdx.x * 256 + threadIdx.x;
    const int b  = n >> 10;
    const int hw = n & 1023;

    const int idx = (int)out[OFF_IDX + n];
    atomicAdd(&g_counts[idx], 1.0f);

    const float*  zbp = z   + (size_t)b * (DDIM * 1024) + hw;
    float*        zq  = out + OFF_ZQ + (size_t)b * (DDIM * 1024) + hw;
    const float4* ev  = (const float4*)(emb + (size_t)idx * DDIM);
    float lsum = 0.0f;
#pragma unroll
    for (int q = 0; q < 16; ++q) {
        float4 e4 = ev[q];
        float ee[4] = { e4.x, e4.y, e4.z, e4.w };
#pragma unroll
        for (int c = 0; c < 4; ++c) {
            int d = q * 4 + c;
            float zv = zbp[d * 1024];
            float diff = zv - ee[c];
            lsum = fmaf(diff, diff, lsum);
            zq[d * 1024] = zv + (ee[c] - zv);   // straight-through, ref arithmetic
            atomicAdd(&g_dw[idx * DDIM + d], zv);
        }
    }
#pragma unroll
    for (int o = 16; o > 0; o >>= 1) lsum += __shfl_xor_sync(0xffffffffu, lsum, o);
    if ((threadIdx.x & 31) == 0) atomicAdd(&g_loss, lsum);
}

// ---------------------------------------------------------------------------
__global__ void vq_finalize1(const float* __restrict__ cs, float* __restrict__ out) {
    __shared__ float red[1024];
    int k = threadIdx.x;
    float ncs = fmaf(0.99f, cs[k], 0.01f * g_counts[k]);
    out[OFF_CS + k] = ncs;
    red[k] = ncs;
    __syncthreads();
#pragma unroll
    for (int s = 512; s > 0; s >>= 1) {
        if (k < s) red[k] += red[k + s];
        __syncthreads();
    }
    if (k == 0) {
        g_nsum = red[0];
        out[OFF_LOSS] = 0.25f * g_loss / 4194304.0f;
    }
}

__global__ void vq_finalize2(const float* __restrict__ ema_w,
                             const float* __restrict__ out_cs_ro,
                             float* __restrict__ out) {
    int i = blockIdx.x * blockDim.x + threadIdx.x;  // 0..65535
    int k = i >> 6;
    float ne = fmaf(0.99f, ema_w[i], 0.01f * g_dw[i]);
    out[OFF_EMAW + i] = ne;
    float ncs = out_cs_ro[OFF_CS + k];
    float nn = g_nsum;
    float csv = (ncs + 1e-5f) / (nn + (float)KCODES * 1e-5f) * nn;
    out[OFF_EMB + i] = ne / csv;
}

// ---------------------------------------------------------------------------
extern "C" void kernel_launch(void* const* d_in, const int* in_sizes, int n_in,
                              void* d_out, int out_size) {
    const float* z    = (const float*)d_in[0];
    const float* emb  = (const float*)d_in[1];
    const float* cs   = (const float*)d_in[2];
    const float* emaw = (const float*)d_in[3];
    float* out = (float*)d_out;

    cudaFuncSetAttribute(vq_mma, cudaFuncAttributeMaxDynamicSharedMemorySize,
                         SMEM_FLOATS * 4);

    vq_prep<<<256, 256>>>(emb);
    vq_mma<<<NVEC / MTILE, 512, SMEM_FLOATS * 4>>>(z, out);
    vq_epi<<<NVEC / 256, 256>>>(z, emb, out);
    vq_finalize1<<<1, 1024>>>(cs, out);
    vq_finalize2<<<NVEC / 1024, 1024>>>(emaw, out, out);
}

// round 6
// speedup vs baseline: 2.4002x; 1.2878x over previous
#include <cuda_runtime.h>
#include <cuda_fp16.h>
#include <cstdint>

// ---------------------------------------------------------------------------
// VectorQuantizerEMA on GB300 — Round 6: persistent fused fp16-mma kernel
//   argmax_k ( z.e_k - |e_k|^2/2 ),  3-way fp16 split (zh.eh + zl.eh + zh.el)
//   + fused epilogue (z_q / loss / counts / dw) + work-stealing CTAs.
// ---------------------------------------------------------------------------

#define KCODES 1024
#define DDIM   64
#define NVEC   65536

#define OFF_ZQ    0
#define OFF_LOSS  4194304
#define OFF_IDX   4194305
#define OFF_CS    4259841
#define OFF_EMAW  4260865
#define OFF_EMB   4326401

#define MTILE   128
#define NITEMS  (NVEC / MTILE)       // 512
#define CHUNK   64
#define NCHUNK  (KCODES / CHUNK)

#define CHUNK_WORDS  4096            // 16 KB per B chunk
#define ZSTRIDE 68
// smem float offsets
#define ZS_OFF   0                   // 128*68 = 8704 floats z stage
#define B_OFF    8704                // 2 x 4096 words B double buffer
#define E2_OFF   16896               // 1024 floats
#define IDX_OFF  17920               // 128 ints
#define SMEM_FLOATS 18048            // 72192 bytes

// Scratch
__device__ float    g_counts[KCODES];
__device__ float    g_dw[KCODES * DDIM];
__device__ float    g_e2[KCODES];
__device__ unsigned g_B[NCHUNK * CHUNK_WORDS];   // 256 KB packed half2
__device__ float    g_loss;
__device__ int      g_work;

// ---------------------------------------------------------------------------
__device__ __forceinline__ unsigned pack_h2(float a, float b) {
    __half ha = __float2half_rn(a), hb = __float2half_rn(b);
    return (unsigned)__half_as_ushort(ha) |
           ((unsigned)__half_as_ushort(hb) << 16);
}

// ---------------------------------------------------------------------------
// Kernel 0: zero scratch, |e|^2, build packed fp16 B fragments (same layout
// as R5: chunk -> 8 tiles x 4 slots x 32 lanes x 4 half2 words, lane-linear).
// ---------------------------------------------------------------------------
__global__ __launch_bounds__(256)
void vq_prep(const float* __restrict__ emb) {
    int i = blockIdx.x * 256 + threadIdx.x;         // 0..65535
    if (i < KCODES * DDIM) g_dw[i] = 0.0f;
    if (i == 0) { g_loss = 0.0f; g_work = 0; }
    if (i < KCODES) {
        g_counts[i] = 0.0f;
        const float* e = emb + i * DDIM;
        float s = 0.0f;
#pragma unroll
        for (int d = 0; d < DDIM; ++d) { float v = e[d]; s = fmaf(v, v, s); }
        g_e2[i] = s;
    }
    {
        int chunk = i >> 12;
        int rem   = i & 4095;
        int s    = rem >> 9;
        int q    = (rem >> 7) & 3;
        int lane = (rem >> 2) & 31;
        int j    = rem & 3;
        int grp = lane >> 2, tig = lane & 3;
        int w = q * 4 + j;
        int bk = w >> 1, h = w & 1;
        int code = chunk * 64 + s * 8 + grp;
        int d = (bk & 3) * 16 + tig * 2 + h * 8;
        float v0 = emb[code * DDIM + d];
        float v1 = emb[code * DDIM + d + 1];
        unsigned o;
        if (bk < 4) {
            o = pack_h2(v0, v1);
        } else {
            float h0 = __half2float(__float2half_rn(v0));
            float h1 = __half2float(__float2half_rn(v1));
            o = pack_h2(v0 - h0, v1 - h1);
        }
        g_B[i] = o;
    }
}

// ---------------------------------------------------------------------------
#define MMAF16(C, A, b0, b1)                                                \
    asm volatile("mma.sync.aligned.m16n8k16.row.col.f32.f16.f16.f32 "       \
                 "{%0,%1,%2,%3}, {%4,%5,%6,%7}, {%8,%9}, {%0,%1,%2,%3};"    \
                 : "+f"(C[0]), "+f"(C[1]), "+f"(C[2]), "+f"(C[3])           \
                 : "r"(A[0]), "r"(A[1]), "r"(A[2]), "r"(A[3]),              \
                   "r"(b0), "r"(b1))

#define ASEL(kt) ((kt) < 4 ? ah[(kt)] : (kt) < 8 ? al[(kt) - 4] : ah[(kt) - 8])

__device__ __forceinline__ void upd(float v, int i, float& b, int& bi) {
    if (v > b) { b = v; bi = i; }   // strict > => first index wins ties
}

// ---------------------------------------------------------------------------
// Kernel 1: persistent fused GEMM + argmax + epilogue.
// 296 CTAs x 256 threads (8 warps x 16 rows), occ 2, work-steal 512 items.
// ---------------------------------------------------------------------------
__global__ __launch_bounds__(256, 2)
void vq_fused(const float* __restrict__ z, const float* __restrict__ emb,
              float* __restrict__ out) {
    extern __shared__ float smem[];
    float* zs   = smem + ZS_OFF;
    float* se2  = smem + E2_OFF;
    int*   sidx = (int*)(smem + IDX_OFF);
    __shared__ int swork;

    const int tid  = threadIdx.x;
    const int wid  = tid >> 5;
    const int lane = tid & 31;
    const int grp  = lane >> 2;
    const int tig  = lane & 3;
    const int row0 = (wid << 4) + grp;        // 0..127 (+8 sibling)

    for (int i = tid; i < KCODES; i += 256) se2[i] = g_e2[i];
    const unsigned sb = (unsigned)__cvta_generic_to_shared(smem);
    const unsigned sbB = sb + B_OFF * 4;

    float lacc = 0.0f;                        // per-thread loss accumulator

    for (;;) {
        if (tid == 0) swork = atomicAdd(&g_work, 1);
        __syncthreads();                      // publish swork; guard smem reuse
        const int item = swork;
        if (item >= NITEMS) break;

        const int n0  = item * MTILE;
        const int zb  = n0 >> 10;
        const int hw0 = n0 & 1023;
        const float* zsrc = z + (size_t)zb * (DDIM * 1024) + hw0;

        // ---- stage z tile: zs[r*68 + d], coalesced over r ----
        for (int i = tid; i < MTILE * DDIM; i += 256) {
            int d = i >> 7, r = i & 127;
            zs[r * ZSTRIDE + d] = zsrc[d * 1024 + r];
        }
        __syncthreads();

        // ---- A fragments (z_hi / z_lo), 4 k16-tiles ----
        unsigned ah[4][4], al[4][4];
#pragma unroll
        for (int kt = 0; kt < 4; ++kt) {
#pragma unroll
            for (int p = 0; p < 4; ++p) {
                int r = row0 + ((p & 1) << 3);
                int c = kt * 16 + tig * 2 + ((p >> 1) << 3);
                float v0 = zs[r * ZSTRIDE + c];
                float v1 = zs[r * ZSTRIDE + c + 1];
                float h0 = __half2float(__float2half_rn(v0));
                float h1 = __half2float(__float2half_rn(v1));
                ah[kt][p] = pack_h2(v0, v1);
                al[kt][p] = pack_h2(v0 - h0, v1 - h1);
            }
        }

        // ---- B chunk 0 ----
        {
            size_t src = __cvta_generic_to_global(g_B);
            for (int i = tid; i < CHUNK_WORDS / 4; i += 256)
                asm volatile("cp.async.ca.shared.global [%0], [%1], 16;"
                             :: "r"(sbB + i * 16), "l"(src + (size_t)i * 16));
            asm volatile("cp.async.commit_group;");
        }

        float best0 = -3.4e38f, best8 = -3.4e38f;
        int   idx0 = 0, idx8 = 0;

        for (int ch = 0; ch < NCHUNK; ++ch) {
            if (ch + 1 < NCHUNK) {
                unsigned dst = sbB + ((ch + 1) & 1) * (CHUNK_WORDS * 4);
                size_t   src = __cvta_generic_to_global(g_B) +
                               (size_t)(ch + 1) * CHUNK_WORDS * 4;
                for (int i = tid; i < CHUNK_WORDS / 4; i += 256)
                    asm volatile("cp.async.ca.shared.global [%0], [%1], 16;"
                                 :: "r"(dst + i * 16), "l"(src + (size_t)i * 16));
                asm volatile("cp.async.commit_group;");
                asm volatile("cp.async.wait_group 1;");
            } else {
                asm volatile("cp.async.wait_group 0;");
            }
            __syncthreads();

            const unsigned bufb = sbB + (ch & 1) * (CHUNK_WORDS * 4) + lane * 16;
#pragma unroll 1
            for (int s = 0; s < 8; s += 2) {
                const int nb0 = ch * CHUNK + s * 8;
                const int nb1 = nb0 + 8;
                float c0[4], c1[4];
                c0[0] = c0[2] = -0.5f * se2[nb0 + 2 * tig];
                c0[1] = c0[3] = -0.5f * se2[nb0 + 2 * tig + 1];
                c1[0] = c1[2] = -0.5f * se2[nb1 + 2 * tig];
                c1[1] = c1[3] = -0.5f * se2[nb1 + 2 * tig + 1];

                unsigned bw0[16], bw1[16];
#pragma unroll
                for (int q = 0; q < 4; ++q) {
                    asm volatile("ld.shared.v4.b32 {%0,%1,%2,%3}, [%4];"
                                 : "=r"(bw0[q * 4]), "=r"(bw0[q * 4 + 1]),
                                   "=r"(bw0[q * 4 + 2]), "=r"(bw0[q * 4 + 3])
                                 : "r"(bufb + (s * 4 + q) * 512));
                    asm volatile("ld.shared.v4.b32 {%0,%1,%2,%3}, [%4];"
                                 : "=r"(bw1[q * 4]), "=r"(bw1[q * 4 + 1]),
                                   "=r"(bw1[q * 4 + 2]), "=r"(bw1[q * 4 + 3])
                                 : "r"(bufb + ((s + 1) * 4 + q) * 512));
                }
#pragma unroll
                for (int kt = 0; kt < 12; ++kt) {
                    const int bi = (kt < 4) ? kt : kt - 4;  // dedup'd e_hi
                    MMAF16(c0, ASEL(kt), bw0[bi * 2], bw0[bi * 2 + 1]);
                    MMAF16(c1, ASEL(kt), bw1[bi * 2], bw1[bi * 2 + 1]);
                }
                upd(c0[0], nb0 + 2 * tig,     best0, idx0);
                upd(c0[1], nb0 + 2 * tig + 1, best0, idx0);
                upd(c0[2], nb0 + 2 * tig,     best8, idx8);
                upd(c0[3], nb0 + 2 * tig + 1, best8, idx8);
                upd(c1[0], nb1 + 2 * tig,     best0, idx0);
                upd(c1[1], nb1 + 2 * tig + 1, best0, idx0);
                upd(c1[2], nb1 + 2 * tig,     best8, idx8);
                upd(c1[3], nb1 + 2 * tig + 1, best8, idx8);
            }
            __syncthreads();
        }

        // ---- argmax across the 4 lanes of each row group ----
#pragma unroll
        for (int m = 1; m <= 2; m <<= 1) {
            float ob = __shfl_xor_sync(0xffffffffu, best0, m);
            int   oi = __shfl_xor_sync(0xffffffffu, idx0,  m);
            if (ob > best0 || (ob == best0 && oi < idx0)) { best0 = ob; idx0 = oi; }
            ob = __shfl_xor_sync(0xffffffffu, best8, m);
            oi = __shfl_xor_sync(0xffffffffu, idx8,  m);
            if (ob > best8 || (ob == best8 && oi < idx8)) { best8 = ob; idx8 = oi; }
        }
        if (tig == 0) {
            sidx[row0]     = idx0;
            sidx[row0 + 8] = idx8;
            out[OFF_IDX + n0 + row0]     = (float)idx0;
            out[OFF_IDX + n0 + row0 + 8] = (float)idx8;
            atomicAdd(&g_counts[idx0], 1.0f);
            atomicAdd(&g_counts[idx8], 1.0f);
        }
        __syncthreads();

        // ---- fused epilogue: z_q, loss, dw (z still staged in smem) ----
        float* zq = out + OFF_ZQ + (size_t)zb * (DDIM * 1024) + hw0;
#pragma unroll 4
        for (int e = tid; e < MTILE * DDIM; e += 256) {
            int d = e >> 7, r = e & 127;
            int idx = sidx[r];
            float zv = zs[r * ZSTRIDE + d];
            float ev = emb[idx * DDIM + d];
            float diff = zv - ev;
            lacc = fmaf(diff, diff, lacc);
            zq[d * 1024 + r] = zv + (ev - zv);   // straight-through, ref arithmetic
            atomicAdd(&g_dw[idx * DDIM + d], zv);
        }
    }

    // one loss atomic per warp for the whole kernel
#pragma unroll
    for (int o = 16; o > 0; o >>= 1) lacc += __shfl_xor_sync(0xffffffffu, lacc, o);
    if ((tid & 31) == 0) atomicAdd(&g_loss, lacc);
}

// ---------------------------------------------------------------------------
// Kernel 2: merged finalize.  64 blocks x 1024 threads; every block
// redundantly computes new_cs + its sum; block 0 also writes new_cs + loss.
// ---------------------------------------------------------------------------
__global__ __launch_bounds__(1024)
void vq_final(const float* __restrict__ cs, const float* __restrict__ ema_w,
              float* __restrict__ out) {
    __shared__ float sncs[1024];
    __shared__ float red[1024];
    int t = threadIdx.x;
    float ncs = fmaf(0.99f, cs[t], 0.01f * g_counts[t]);
    sncs[t] = ncs;
    red[t] = ncs;
    __syncthreads();
#pragma unroll
    for (int s = 512; s > 0; s >>= 1) {
        if (t < s) red[t] += red[t + s];
        __syncthreads();
    }
    float nn = red[0];

    if (blockIdx.x == 0) {
        out[OFF_CS + t] = ncs;
        if (t == 0) out[OFF_LOSS] = 0.25f * g_loss / 4194304.0f;
    }

    int i = blockIdx.x * 1024 + t;          // 0..65535
    int k = i >> 6;
    float ne = fmaf(0.99f, ema_w[i], 0.01f * g_dw[i]);
    out[OFF_EMAW + i] = ne;
    float csv = (sncs[k] + 1e-5f) / (nn + (float)KCODES * 1e-5f) * nn;
    out[OFF_EMB + i] = ne / csv;
}

// ---------------------------------------------------------------------------
extern "C" void kernel_launch(void* const* d_in, const int* in_sizes, int n_in,
                              void* d_out, int out_size) {
    const float* z    = (const float*)d_in[0];
    const float* emb  = (const float*)d_in[1];
    const float* cs   = (const float*)d_in[2];
    const float* emaw = (const float*)d_in[3];
    float* out = (float*)d_out;

    cudaFuncSetAttribute(vq_fused, cudaFuncAttributeMaxDynamicSharedMemorySize,
                         SMEM_FLOATS * 4);

    vq_prep<<<256, 256>>>(emb);
    vq_fused<<<296, 256, SMEM_FLOATS * 4>>>(z, emb, out);
    vq_final<<<64, 1024>>>(cs, emaw, out);
}

// round 8
// speedup vs baseline: 3.4800x; 1.4499x over previous
#include <cuda_runtime.h>
#include <cuda_fp16.h>
#include <cstdint>

// ---------------------------------------------------------------------------
// VectorQuantizerEMA on GB300 — Round 8: R6 numerics (exact e2 order) +
// vectorized dw atomics (red.v4) + fast prep (smem-staged coalesced e2,
// g_dw zeroing moved to vq_final).
//   argmax_k ( z.e_k - |e_k|^2/2 ),  3-way fp16 split (zh.eh + zl.eh + zh.el)
// ---------------------------------------------------------------------------

#define KCODES 1024
#define DDIM   64
#define NVEC   65536

#define OFF_ZQ    0
#define OFF_LOSS  4194304
#define OFF_IDX   4194305
#define OFF_CS    4259841
#define OFF_EMAW  4260865
#define OFF_EMB   4326401

#define MTILE   128
#define NITEMS  (NVEC / MTILE)       // 512
#define CHUNK   64
#define NCHUNK  (KCODES / CHUNK)

#define CHUNK_WORDS  4096            // 16 KB per B chunk
#define ZSTRIDE 68
// smem float offsets (vq_fused)
#define ZS_OFF   0                   // 128*68 = 8704 floats z stage
#define B_OFF    8704                // 2 x 4096 words B double buffer
#define E2_OFF   16896               // 1024 floats
#define IDX_OFF  17920               // 128 ints
#define SMEM_FLOATS 18048            // 72192 bytes

// Scratch
__device__ float    g_counts[KCODES];
__device__ float    g_dw[KCODES * DDIM];   // zeroed at END of vq_final
__device__ float    g_e2[KCODES];
__device__ unsigned g_B[NCHUNK * CHUNK_WORDS];   // 256 KB packed half2
__device__ float    g_loss;
__device__ int      g_work;

// ---------------------------------------------------------------------------
__device__ __forceinline__ unsigned pack_h2(float a, float b) {
    __half ha = __float2half_rn(a), hb = __float2half_rn(b);
    return (unsigned)__half_as_ushort(ha) |
           ((unsigned)__half_as_ushort(hb) << 16);
}

// ---------------------------------------------------------------------------
// Kernel 0: counts/scalars zero, |e|^2, packed fp16 B build.
// e2: blocks 0..7 stage 128 codes x 64 floats coalesced into smem (+65 pad),
// then thread t sums ITS code with the exact same sequential fmaf chain as
// the R6 passing kernel (summation order is correctness-relevant: it decides
// near-tie argmins).
// ---------------------------------------------------------------------------
__global__ __launch_bounds__(256)
void vq_prep(const float* __restrict__ emb) {
    __shared__ float es[128 * 65];
    const int t = threadIdx.x;
    const int b = blockIdx.x;
    const int i = b * 256 + t;                      // 0..65535

    if (i < KCODES) g_counts[i] = 0.0f;
    if (i == 0) { g_loss = 0.0f; g_work = 0; }

    if (b < 8) {
        const float* src = emb + b * 128 * DDIM;
        for (int j = t; j < 128 * DDIM; j += 256) {
            int code = j >> 6, d = j & 63;
            es[code * 65 + d] = src[j];             // coalesced read
        }
        __syncthreads();
        if (t < 128) {
            float s = 0.0f;
#pragma unroll
            for (int d = 0; d < DDIM; ++d) {
                float v = es[t * 65 + d];
                s = fmaf(v, v, s);                  // EXACT R6 order
            }
            g_e2[b * 128 + t] = s;
        }
    }

    // ---- B build: one word per thread (layout as R5/R6) ----
    {
        int chunk = i >> 12;
        int rem   = i & 4095;
        int s    = rem >> 9;
        int q    = (rem >> 7) & 3;
        int lane = (rem >> 2) & 31;
        int j    = rem & 3;
        int grp = lane >> 2, tig = lane & 3;
        int w = q * 4 + j;
        int bk = w >> 1, h = w & 1;
        int code = chunk * 64 + s * 8 + grp;
        int d = (bk & 3) * 16 + tig * 2 + h * 8;
        float v0 = emb[code * DDIM + d];
        float v1 = emb[code * DDIM + d + 1];
        unsigned o;
        if (bk < 4) {
            o = pack_h2(v0, v1);
        } else {
            float h0 = __half2float(__float2half_rn(v0));
            float h1 = __half2float(__float2half_rn(v1));
            o = pack_h2(v0 - h0, v1 - h1);
        }
        g_B[i] = o;
    }
}

// ---------------------------------------------------------------------------
#define MMAF16(C, A, b0, b1)                                                \
    asm volatile("mma.sync.aligned.m16n8k16.row.col.f32.f16.f16.f32 "       \
                 "{%0,%1,%2,%3}, {%4,%5,%6,%7}, {%8,%9}, {%0,%1,%2,%3};"    \
                 : "+f"(C[0]), "+f"(C[1]), "+f"(C[2]), "+f"(C[3])           \
                 : "r"(A[0]), "r"(A[1]), "r"(A[2]), "r"(A[3]),              \
                   "r"(b0), "r"(b1))

#define ASEL(kt) ((kt) < 4 ? ah[(kt)] : (kt) < 8 ? al[(kt) - 4] : ah[(kt) - 8])

__device__ __forceinline__ void upd(float v, int i, float& b, int& bi) {
    if (v > b) { b = v; bi = i; }   // strict > => first index wins ties
}

// ---------------------------------------------------------------------------
// Kernel 1: persistent fused GEMM + argmax + epilogue.
// 296 CTAs x 256 threads (8 warps x 16 rows), occ 2, work-steal 512 items.
// ---------------------------------------------------------------------------
__global__ __launch_bounds__(256, 2)
void vq_fused(const float* __restrict__ z, const float* __restrict__ emb,
              float* __restrict__ out) {
    extern __shared__ float smem[];
    float* zs   = smem + ZS_OFF;
    float* se2  = smem + E2_OFF;
    int*   sidx = (int*)(smem + IDX_OFF);
    __shared__ int swork;

    const int tid  = threadIdx.x;
    const int wid  = tid >> 5;
    const int lane = tid & 31;
    const int grp  = lane >> 2;
    const int tig  = lane & 3;
    const int row0 = (wid << 4) + grp;        // 0..127 (+8 sibling)

    for (int i = tid; i < KCODES; i += 256) se2[i] = g_e2[i];
    const unsigned sb = (unsigned)__cvta_generic_to_shared(smem);
    const unsigned sbB = sb + B_OFF * 4;

    float lacc = 0.0f;                        // per-thread loss accumulator

    for (;;) {
        if (tid == 0) swork = atomicAdd(&g_work, 1);
        __syncthreads();                      // publish swork; guard smem reuse
        const int item = swork;
        if (item >= NITEMS) break;

        const int n0  = item * MTILE;
        const int zb  = n0 >> 10;
        const int hw0 = n0 & 1023;
        const float* zsrc = z + (size_t)zb * (DDIM * 1024) + hw0;

        // ---- stage z tile: zs[r*68 + d], coalesced over r ----
        for (int i = tid; i < MTILE * DDIM; i += 256) {
            int d = i >> 7, r = i & 127;
            zs[r * ZSTRIDE + d] = zsrc[d * 1024 + r];
        }
        __syncthreads();

        // ---- A fragments (z_hi / z_lo), 4 k16-tiles ----
        unsigned ah[4][4], al[4][4];
#pragma unroll
        for (int kt = 0; kt < 4; ++kt) {
#pragma unroll
            for (int p = 0; p < 4; ++p) {
                int r = row0 + ((p & 1) << 3);
                int c = kt * 16 + tig * 2 + ((p >> 1) << 3);
                float v0 = zs[r * ZSTRIDE + c];
                float v1 = zs[r * ZSTRIDE + c + 1];
                float h0 = __half2float(__float2half_rn(v0));
                float h1 = __half2float(__float2half_rn(v1));
                ah[kt][p] = pack_h2(v0, v1);
                al[kt][p] = pack_h2(v0 - h0, v1 - h1);
            }
        }

        // ---- B chunk 0 ----
        {
            size_t src = __cvta_generic_to_global(g_B);
            for (int i = tid; i < CHUNK_WORDS / 4; i += 256)
                asm volatile("cp.async.ca.shared.global [%0], [%1], 16;"
                             :: "r"(sbB + i * 16), "l"(src + (size_t)i * 16));
            asm volatile("cp.async.commit_group;");
        }

        float best0 = -3.4e38f, best8 = -3.4e38f;
        int   idx0 = 0, idx8 = 0;

        for (int ch = 0; ch < NCHUNK; ++ch) {
            if (ch + 1 < NCHUNK) {
                unsigned dst = sbB + ((ch + 1) & 1) * (CHUNK_WORDS * 4);
                size_t   src = __cvta_generic_to_global(g_B) +
                               (size_t)(ch + 1) * CHUNK_WORDS * 4;
                for (int i = tid; i < CHUNK_WORDS / 4; i += 256)
                    asm volatile("cp.async.ca.shared.global [%0], [%1], 16;"
                                 :: "r"(dst + i * 16), "l"(src + (size_t)i * 16));
                asm volatile("cp.async.commit_group;");
                asm volatile("cp.async.wait_group 1;");
            } else {
                asm volatile("cp.async.wait_group 0;");
            }
            __syncthreads();

            const unsigned bufb = sbB + (ch & 1) * (CHUNK_WORDS * 4) + lane * 16;
#pragma unroll 1
            for (int s = 0; s < 8; s += 2) {
                const int nb0 = ch * CHUNK + s * 8;
                const int nb1 = nb0 + 8;
                float c0[4], c1[4];
                c0[0] = c0[2] = -0.5f * se2[nb0 + 2 * tig];
                c0[1] = c0[3] = -0.5f * se2[nb0 + 2 * tig + 1];
                c1[0] = c1[2] = -0.5f * se2[nb1 + 2 * tig];
                c1[1] = c1[3] = -0.5f * se2[nb1 + 2 * tig + 1];

                unsigned bw0[16], bw1[16];
#pragma unroll
                for (int q = 0; q < 4; ++q) {
                    asm volatile("ld.shared.v4.b32 {%0,%1,%2,%3}, [%4];"
                                 : "=r"(bw0[q * 4]), "=r"(bw0[q * 4 + 1]),
                                   "=r"(bw0[q * 4 + 2]), "=r"(bw0[q * 4 + 3])
                                 : "r"(bufb + (s * 4 + q) * 512));
                    asm volatile("ld.shared.v4.b32 {%0,%1,%2,%3}, [%4];"
                                 : "=r"(bw1[q * 4]), "=r"(bw1[q * 4 + 1]),
                                   "=r"(bw1[q * 4 + 2]), "=r"(bw1[q * 4 + 3])
                                 : "r"(bufb + ((s + 1) * 4 + q) * 512));
                }
#pragma unroll
                for (int kt = 0; kt < 12; ++kt) {
                    const int bi = (kt < 4) ? kt : kt - 4;  // dedup'd e_hi
                    MMAF16(c0, ASEL(kt), bw0[bi * 2], bw0[bi * 2 + 1]);
                    MMAF16(c1, ASEL(kt), bw1[bi * 2], bw1[bi * 2 + 1]);
                }
                upd(c0[0], nb0 + 2 * tig,     best0, idx0);
                upd(c0[1], nb0 + 2 * tig + 1, best0, idx0);
                upd(c0[2], nb0 + 2 * tig,     best8, idx8);
                upd(c0[3], nb0 + 2 * tig + 1, best8, idx8);
                upd(c1[0], nb1 + 2 * tig,     best0, idx0);
                upd(c1[1], nb1 + 2 * tig + 1, best0, idx0);
                upd(c1[2], nb1 + 2 * tig,     best8, idx8);
                upd(c1[3], nb1 + 2 * tig + 1, best8, idx8);
            }
            __syncthreads();
        }

        // ---- argmax across the 4 lanes of each row group ----
#pragma unroll
        for (int m = 1; m <= 2; m <<= 1) {
            float ob = __shfl_xor_sync(0xffffffffu, best0, m);
            int   oi = __shfl_xor_sync(0xffffffffu, idx0,  m);
            if (ob > best0 || (ob == best0 && oi < idx0)) { best0 = ob; idx0 = oi; }
            ob = __shfl_xor_sync(0xffffffffu, best8, m);
            oi = __shfl_xor_sync(0xffffffffu, idx8,  m);
            if (ob > best8 || (ob == best8 && oi < idx8)) { best8 = ob; idx8 = oi; }
        }
        if (tig == 0) {
            sidx[row0]     = idx0;
            sidx[row0 + 8] = idx8;
            out[OFF_IDX + n0 + row0]     = (float)idx0;
            out[OFF_IDX + n0 + row0 + 8] = (float)idx8;
            atomicAdd(&g_counts[idx0], 1.0f);
            atomicAdd(&g_counts[idx8], 1.0f);
        }
        __syncthreads();

        // ---- fused epilogue: unit = (row, 4 consecutive d) ----
        // LDS.128 zs + LDG.128 emb + 4 coalesced STG + one red.v4 to g_dw.
        float* zq = out + OFF_ZQ + (size_t)zb * (DDIM * 1024) + hw0;
        const float4* embv = (const float4*)emb;
#pragma unroll 2
        for (int u = tid; u < MTILE * (DDIM / 4); u += 256) {
            int r = u & 127, dg = u >> 7;           // dg 0..15
            int idx = sidx[r];
            float4 zv = *(const float4*)&zs[r * ZSTRIDE + dg * 4];
            float4 ev = __ldg(&embv[idx * (DDIM / 4) + dg]);
            float d0 = zv.x - ev.x; lacc = fmaf(d0, d0, lacc);
            float d1 = zv.y - ev.y; lacc = fmaf(d1, d1, lacc);
            float d2 = zv.z - ev.z; lacc = fmaf(d2, d2, lacc);
            float d3 = zv.w - ev.w; lacc = fmaf(d3, d3, lacc);
            zq[(dg * 4 + 0) * 1024 + r] = zv.x + (ev.x - zv.x);
            zq[(dg * 4 + 1) * 1024 + r] = zv.y + (ev.y - zv.y);
            zq[(dg * 4 + 2) * 1024 + r] = zv.z + (ev.z - zv.z);
            zq[(dg * 4 + 3) * 1024 + r] = zv.w + (ev.w - zv.w);
            asm volatile("red.global.add.v4.f32 [%0], {%1, %2, %3, %4};"
                         :: "l"(&g_dw[idx * DDIM + dg * 4]),
                            "f"(zv.x), "f"(zv.y), "f"(zv.z), "f"(zv.w)
                         : "memory");
        }
    }

    // one loss atomic per warp for the whole kernel
#pragma unroll
    for (int o = 16; o > 0; o >>= 1) lacc += __shfl_xor_sync(0xffffffffu, lacc, o);
    if ((tid & 31) == 0) atomicAdd(&g_loss, lacc);
}

// ---------------------------------------------------------------------------
// Kernel 2: merged finalize; also re-zeroes g_dw for the next graph replay
// (thread i is the only reader of g_dw[i] -> race-free).
// ---------------------------------------------------------------------------
__global__ __launch_bounds__(1024)
void vq_final(const float* __restrict__ cs, const float* __restrict__ ema_w,
              float* __restrict__ out) {
    __shared__ float sncs[1024];
    __shared__ float red[1024];
    int t = threadIdx.x;
    float ncs = fmaf(0.99f, cs[t], 0.01f * g_counts[t]);
    sncs[t] = ncs;
    red[t] = ncs;
    __syncthreads();
#pragma unroll
    for (int s = 512; s > 0; s >>= 1) {
        if (t < s) red[t] += red[t + s];
        __syncthreads();
    }
    float nn = red[0];

    if (blockIdx.x == 0) {
        out[OFF_CS + t] = ncs;
        if (t == 0) out[OFF_LOSS] = 0.25f * g_loss / 4194304.0f;
    }

    int i = blockIdx.x * 1024 + t;          // 0..65535
    int k = i >> 6;
    float ne = fmaf(0.99f, ema_w[i], 0.01f * g_dw[i]);
    g_dw[i] = 0.0f;                          // reset for next replay
    out[OFF_EMAW + i] = ne;
    float csv = (sncs[k] + 1e-5f) / (nn + (float)KCODES * 1e-5f) * nn;
    out[OFF_EMB + i] = ne / csv;
}

// ---------------------------------------------------------------------------
extern "C" void kernel_launch(void* const* d_in, const int* in_sizes, int n_in,
                              void* d_out, int out_size) {
    const float* z    = (const float*)d_in[0];
    const float* emb  = (const float*)d_in[1];
    const float* cs   = (const float*)d_in[2];
    const float* emaw = (const float*)d_in[3];
    float* out = (float*)d_out;

    cudaFuncSetAttribute(vq_fused, cudaFuncAttributeMaxDynamicSharedMemorySize,
                         SMEM_FLOATS * 4);

    vq_prep<<<256, 256>>>(emb);
    vq_fused<<<296, 256, SMEM_FLOATS * 4>>>(z, emb, out);
    vq_final<<<64, 1024>>>(cs, emaw, out);
}